// round 9
// baseline (speedup 1.0000x reference)
#include <cuda_runtime.h>
#include <cuda_bf16.h>

// EdgeEncoding: out[h,i,j] = sum_e coeff[e]*enc[node[e],h], enc = edge_attr@W.T+b.
// Factorized: out[h,p] = g[p].W[h] + b[h]*s[p]; g[p]=sum c_e*edge_attr[node_e], s[p]=sum c_e.
// pair_idx sorted over the real prefix; padding tail coeff==0 (flushes suppressed by s==0).
// Pass1: warp-cooperative segmented reduce-by-key (8 items/lane, truncated Kogge-Stone).
// NEW: forked-stream overlap. pass1 split at entry Ma; after pass1_A all pairs with
// key < key(Ma) are final. pass2_low (pairs [0,Pmid), Pmid << key(Ma)) overlaps pass1_B.

#define NNODES 768
#define NN (NNODES * NNODES)   // 589824
#define NH 32

#define BT 256                  // 8 warps
#define IPL 8                   // items per lane
#define CHUNK (32 * IPL)        // 256 entries per warp
#define TILE ((BT / 32) * CHUNK) // 2048 entries per block

#define BT2 256
#define PP  2
#define PMID 235520             // 460*512, ~0.40*NN; safe: key(0.55*M) >= 0.55*NN

// Fused scratch: g (float4[NN]) then s (float[NN]); zeroed by one memset node.
__device__ __align__(16) float d_buf[NN * 5];
#define D_G ((float4*)d_buf)
#define D_S (d_buf + (size_t)NN * 4)

// Branchless predicated flush (exclusive interior segments): no BSSY/BSYNC.
__device__ __forceinline__ void pred_flush(int doit, int key,
                                           float ax, float ay, float az, float aw, float as)
{
    unsigned long long ga = (unsigned long long)(D_G + key);
    unsigned long long sa = (unsigned long long)(D_S + key);
    asm volatile(
        "{\n\t.reg .pred p;\n\t"
        "setp.ne.s32 p, %0, 0;\n\t"
        "@p st.global.v4.f32 [%1], {%3, %4, %5, %6};\n\t"
        "@p st.global.f32 [%2], %7;\n\t}"
        :: "r"(doit), "l"(ga), "l"(sa),
           "f"(ax), "f"(ay), "f"(az), "f"(aw), "f"(as));
}

__device__ __forceinline__ void flush_maybe_shared(bool shared_seg, int key,
                                                   float ax, float ay, float az,
                                                   float aw, float as)
{
    float* gp = reinterpret_cast<float*>(&D_G[key]);
    if (shared_seg) {
        atomicAdd(gp + 0, ax); atomicAdd(gp + 1, ay);
        atomicAdd(gp + 2, az); atomicAdd(gp + 3, aw);
        atomicAdd(&D_S[key], as);
    } else {
        D_G[key] = make_float4(ax, ay, az, aw);
        D_S[key] = as;
    }
}

#define KS_STEP(d)                                                         \
    do {                                                                   \
        int   sk = __shfl_up_sync(FULL, tkey, d);                          \
        float sx = __shfl_up_sync(FULL, ax, d);                            \
        float sy = __shfl_up_sync(FULL, ay, d);                            \
        float sz = __shfl_up_sync(FULL, az, d);                            \
        float sw = __shfl_up_sync(FULL, aw, d);                            \
        float ss = __shfl_up_sync(FULL, as, d);                            \
        bool add = (lane >= d) && (sk == tkey);                            \
        ax += add ? sx : 0.f;                                              \
        ay += add ? sy : 0.f;                                              \
        az += add ? sz : 0.f;                                              \
        aw += add ? sw : 0.f;                                              \
        as += add ? ss : 0.f;                                              \
    } while (0)

// ---------------------------------------------------------------------------
// Pass 1 over entry range [start, end). Segments straddling `end` are flushed
// exclusively here and continued by the next range via atomicAdd (ranges are
// serialized on the stream, so the store->atomic order is guaranteed).
// ---------------------------------------------------------------------------
__global__ void __launch_bounds__(BT) pass1_kernel(
    const int*   __restrict__ pair_idx,
    const int*   __restrict__ node_idx,
    const float* __restrict__ coeff,
    const float* __restrict__ edge_attr,   // [768,4]
    int start, int end)
{
    const int tile0 = start + blockIdx.x * TILE;
    if (tile0 >= end) return;
    // Skip all-padding blocks (real coeffs strictly positive, padding is a suffix).
    if (tile0 > 0 && __ldg(&coeff[tile0]) == 0.f) return;

    __shared__ float4 sea[NNODES];   // 12 KB
    const int tid = threadIdx.x;
    for (int i = tid; i < NNODES; i += BT)
        sea[i] = reinterpret_cast<const float4*>(edge_attr)[i];
    __syncthreads();

    const int lane = tid & 31;
    const int warp = tid >> 5;
    const unsigned FULL = 0xffffffffu;

    const int base = tile0 + warp * CHUNK;
    if (base >= end) return;
    const int e0 = base + lane * IPL;

    // --- load 8 entries: 2 x int4 per array (streaming) ---
    int   pk[IPL], nk[IPL];
    float ck[IPL];
    if (base + CHUNK <= end) {
        #pragma unroll
        for (int h = 0; h < 2; h++) {
            int4   pv = __ldcs(reinterpret_cast<const int4*>(pair_idx + e0) + h);
            int4   nv = __ldcs(reinterpret_cast<const int4*>(node_idx + e0) + h);
            float4 cv = __ldcs(reinterpret_cast<const float4*>(coeff + e0) + h);
            pk[4*h+0] = pv.x; pk[4*h+1] = pv.y; pk[4*h+2] = pv.z; pk[4*h+3] = pv.w;
            nk[4*h+0] = nv.x; nk[4*h+1] = nv.y; nk[4*h+2] = nv.z; nk[4*h+3] = nv.w;
            ck[4*h+0] = cv.x; ck[4*h+1] = cv.y; ck[4*h+2] = cv.z; ck[4*h+3] = cv.w;
        }
    } else {
        #pragma unroll
        for (int k = 0; k < IPL; k++) {
            int g = e0 + k;
            bool ok = (g < end);
            pk[k] = ok ? __ldg(&pair_idx[g]) : 0;
            nk[k] = ok ? __ldg(&node_idx[g]) : 0;
            ck[k] = ok ? __ldg(&coeff[g])    : 0.f;
        }
    }

    // warp neighbor keys (range-local: straddles handled by store-then-atomic)
    int pv0 = 0;
    if (lane == 0)  pv0 = (base > 0) ? __ldg(&pair_idx[base - 1]) : -3;
    const int prevk = __shfl_sync(FULL, pv0, 0);
    int nv31 = 0;
    if (lane == 31) nv31 = (base + CHUNK < end) ? __ldg(&pair_idx[base + CHUNK]) : -3;
    const int nextk = __shfl_sync(FULL, nv31, 31);

    // --- per-lane scan of 8 items ---
    const int headkey = pk[0];
    int   cur = pk[0];
    float4 ea0 = sea[nk[0]];
    float c0 = ck[0];
    float ax = c0 * ea0.x, ay = c0 * ea0.y, az = c0 * ea0.z, aw = c0 * ea0.w, as = c0;
    int   segcnt = 0;
    int   hkey = 0;
    float hx = 0.f, hy = 0.f, hz = 0.f, hw = 0.f, hs = 0.f;

    #pragma unroll
    for (int k = 1; k < IPL; k++) {
        int  key = pk[k];
        bool neq = (key != cur);
        int doflush = (int)(neq & (segcnt > 0) & (as != 0.f));
        pred_flush(doflush, cur, ax, ay, az, aw, as);
        bool stash = neq & (segcnt == 0);
        hkey = stash ? cur : hkey;
        hx = stash ? ax : hx; hy = stash ? ay : hy; hz = stash ? az : hz;
        hw = stash ? aw : hw; hs = stash ? as : hs;
        segcnt += (int)neq;
        float  cc = ck[k];
        float4 e  = sea[nk[k]];
        ax = fmaf(cc, e.x, neq ? 0.f : ax);
        ay = fmaf(cc, e.y, neq ? 0.f : ay);
        az = fmaf(cc, e.z, neq ? 0.f : az);
        aw = fmaf(cc, e.w, neq ? 0.f : aw);
        as = cc + (neq ? 0.f : as);
        cur = key;
    }
    const int tkey = cur;

    // --- Kogge-Stone with warp-uniform truncation (segments are short) ---
    KS_STEP(1);
    KS_STEP(2);
    {
        int k4 = __shfl_up_sync(FULL, tkey, 4);
        if (__any_sync(FULL, (lane >= 4) && (k4 == tkey))) {
            KS_STEP(4);
            int k8 = __shfl_up_sync(FULL, tkey, 8);
            if (__any_sync(FULL, (lane >= 8) && (k8 == tkey))) {
                KS_STEP(8);
                KS_STEP(16);
            }
        }
    }

    int   tkp = __shfl_up_sync(FULL, tkey, 1);
    float ypx = __shfl_up_sync(FULL, ax, 1);
    float ypy = __shfl_up_sync(FULL, ay, 1);
    float ypz = __shfl_up_sync(FULL, az, 1);
    float ypw = __shfl_up_sync(FULL, aw, 1);
    float yps = __shfl_up_sync(FULL, as, 1);
    int   hkn = __shfl_down_sync(FULL, headkey, 1);

    if (segcnt > 0) {
        bool cge = (lane > 0) && (hkey == tkp);
        float fx = hx + (cge ? ypx : 0.f);
        float fy = hy + (cge ? ypy : 0.f);
        float fz = hz + (cge ? ypz : 0.f);
        float fw = hw + (cge ? ypw : 0.f);
        float fs = hs + (cge ? yps : 0.f);
        if (fs != 0.f)
            flush_maybe_shared(hkey == prevk, hkey, fx, fy, fz, fw, fs);
    }
    bool closes = (lane == 31) || (hkn != tkey);
    if (closes && as != 0.f) {
        bool shared_seg = (tkey == prevk) || ((lane == 31) && (tkey == nextk));
        flush_maybe_shared(shared_seg, tkey, ax, ay, az, aw, as);
    }
}

// ---------------------------------------------------------------------------
// Pass 2 over pair range [p0, p0 + gridDim*BT2*PP)
// ---------------------------------------------------------------------------
__global__ void __launch_bounds__(BT2) pass2_kernel(
    const float* __restrict__ W,   // [32,4]
    const float* __restrict__ b,   // [32]
    float* __restrict__ out,       // [32, 768*768]
    int p0)
{
    __shared__ float sW[NH * 4];
    __shared__ float sb[NH];
    int tid = threadIdx.x;
    if (tid < NH * 4) sW[tid] = W[tid];
    if (tid < NH)     sb[tid] = b[tid];
    __syncthreads();

    int p = p0 + (blockIdx.x * BT2 + tid) * PP;
    float4 g0 = __ldcs(&D_G[p + 0]);
    float4 g1 = __ldcs(&D_G[p + 1]);
    float2 sv = __ldcs(reinterpret_cast<const float2*>(D_S) + (p >> 1));

    #pragma unroll 8
    for (int h = 0; h < NH; h++) {
        float w0 = sW[4 * h + 0], w1 = sW[4 * h + 1];
        float w2 = sW[4 * h + 2], w3 = sW[4 * h + 3];
        float bh = sb[h];
        float2 r;
        r.x = fmaf(g0.x, w0, fmaf(g0.y, w1, fmaf(g0.z, w2, fmaf(g0.w, w3, sv.x * bh))));
        r.y = fmaf(g1.x, w0, fmaf(g1.y, w1, fmaf(g1.z, w2, fmaf(g1.w, w3, sv.y * bh))));
        __stcs(reinterpret_cast<float2*>(out) + ((h * NN + p) >> 1), r);
    }
}

// ---------------------------------------------------------------------------
// kernel_launch: memset -> pass1_A -> { pass1_B || pass2_low } -> pass2_high
// ---------------------------------------------------------------------------
extern "C" void kernel_launch(void* const* d_in, const int* in_sizes, int n_in,
                              void* d_out, int out_size)
{
    const float* edge_attr = nullptr;
    const float* W = nullptr;
    const float* b = nullptr;
    const int*   pair = nullptr;
    const int*   node = nullptr;
    const float* coeff = nullptr;
    int M = 0;
    int bigSeen = 0;

    for (int i = 0; i < n_in; i++) {
        int s = in_sizes[i];
        if (s == NNODES * 4)      edge_attr = (const float*)d_in[i];
        else if (s == NH * 4)     W = (const float*)d_in[i];
        else if (s == NH)         b = (const float*)d_in[i];
        else if (s >= 1000000) {
            if (bigSeen == 0)      pair  = (const int*)d_in[i];
            else if (bigSeen == 1) node  = (const int*)d_in[i];
            else if (bigSeen == 2) { coeff = (const float*)d_in[i]; M = s; }
            bigSeen++;
        }
    }

    // Fork resources (created per call; tiny, not device-array allocation).
    cudaStream_t s2;
    cudaEvent_t evA, evL;
    cudaStreamCreateWithFlags(&s2, cudaStreamNonBlocking);
    cudaEventCreateWithFlags(&evA, cudaEventDisableTiming);
    cudaEventCreateWithFlags(&evL, cudaEventDisableTiming);

    void* bufp = nullptr;
    cudaGetSymbolAddress(&bufp, d_buf);
    cudaMemsetAsync(bufp, 0, sizeof(float) * (size_t)NN * 5);

    // Entry split: Ma = 55% of M rounded to TILE. All keys < PMID (=0.40*NN)
    // have their entries entirely within [0, Ma) with wide margin.
    int Ma = (int)(((long long)M * 55) / 100);
    Ma = (Ma / TILE) * TILE;
    if (Ma <= 0) Ma = TILE;
    if (Ma > M) Ma = M;

    int gA = (Ma + TILE - 1) / TILE;
    int gB = (M - Ma + TILE - 1) / TILE;

    pass1_kernel<<<gA, BT>>>(pair, node, coeff, edge_attr, 0, Ma);
    cudaEventRecord(evA, 0);

    if (gB > 0)
        pass1_kernel<<<gB, BT>>>(pair, node, coeff, edge_attr, Ma, M);

    // pass2_low overlaps pass1_B on stream s2.
    cudaStreamWaitEvent(s2, evA, 0);
    int gL = PMID / (BT2 * PP);              // 460
    pass2_kernel<<<gL, BT2, 0, s2>>>(W, b, (float*)d_out, 0);
    cudaEventRecord(evL, s2);

    int gH = (NN - PMID) / (BT2 * PP);       // 692
    pass2_kernel<<<gH, BT2>>>(W, b, (float*)d_out, PMID);

    // Join forked stream back into the capture-origin stream.
    cudaStreamWaitEvent(0, evL, 0);
}